// round 15
// baseline (speedup 1.0000x reference)
#include <cuda_runtime.h>
#include <cstdint>

#define N_NODES 50000
#define N_EDGES 800000
#define IN_DIM  8
#define EDGE_DIM 4
#define HIDDEN  16

// ---------------- scratch (device globals; no allocation allowed) ----------------
__device__ float g_x1 [N_NODES * HIDDEN];           // layer-0 output
__device__ float g_agg[N_NODES * HIDDEN];           // scatter accumulator
__device__ float g_Y  [N_NODES * HIDDEN * HIDDEN];  // per-node contracted weights [n][k][o]
__device__ float g_B  [N_NODES * HIDDEN];           // per-node contracted bias    [n][o]
__device__ int   g_deg   [N_NODES];                 // out-degree (src histogram)
__device__ int   g_cnti  [N_NODES];                 // in-degree  (dst histogram)
__device__ int   g_rowptr[N_NODES + 1];             // CSR row pointers (by src)
__device__ int   g_pos   [N_NODES];                 // scatter cursors
__device__ int   g_eidx  [N_EDGES];                 // edge ids grouped by src

__device__ __forceinline__ float sigmoidf_(float x) {
    return 1.0f / (1.0f + __expf(-x));
}

// ---------------- zero ----------------
__global__ void zero_kernel() {
    int i = blockIdx.x * blockDim.x + threadIdx.x;
    if (i < N_NODES * HIDDEN) g_agg[i] = 0.0f;
    if (i < N_NODES) { g_deg[i] = 0; g_cnti[i] = 0; }
}

// ---------------- histogram (src out-degree, dst in-degree) ----------------
__global__ void hist_kernel(const int* __restrict__ ei) {
    int e = blockIdx.x * blockDim.x + threadIdx.x;
    if (e >= N_EDGES) return;
    atomicAdd(&g_deg [ei[e]], 1);
    atomicAdd(&g_cnti[ei[N_EDGES + e]], 1);
}

// ---------------- exclusive scan of degrees -> rowptr, pos ----------------
__global__ void __launch_bounds__(1024)
scan_kernel() {
    __shared__ int part[1024];
    const int t = threadIdx.x;
    const int CH = (N_NODES + 1023) / 1024;          // 49
    const int beg = t * CH;
    const int end = min(beg + CH, N_NODES);
    int s = 0;
    for (int i = beg; i < end; i++) s += g_deg[i];
    part[t] = s;
    __syncthreads();
    for (int off = 1; off < 1024; off <<= 1) {
        int v = (t >= off) ? part[t - off] : 0;
        __syncthreads();
        part[t] += v;
        __syncthreads();
    }
    int run = (t == 0) ? 0 : part[t - 1];
    for (int i = beg; i < end; i++) {
        g_rowptr[i] = run;
        g_pos[i]    = run;
        run += g_deg[i];
    }
    if (t == 1023) g_rowptr[N_NODES] = part[1023];
}

// ---------------- scatter edge ids into CSR order ----------------
__global__ void scatter_kernel(const int* __restrict__ ei) {
    int e = blockIdx.x * blockDim.x + threadIdx.x;
    if (e >= N_EDGES) return;
    int p = atomicAdd(&g_pos[ei[e]], 1);
    g_eidx[p] = e;
}

// ---------------- Y precompute ----------------
// Y[n,k,o] = sum_i x[n,i] * W2[k, i*16+o];  B[n,o] = sum_i x[n,i] * b2[i*16+o]
template<int DIN>
__global__ void __launch_bounds__(256)
y_kernel(const float* __restrict__ xin,
         const float* __restrict__ W2, const float* __restrict__ b2)
{
    constexpr int C = DIN * HIDDEN;
    constexpr int PAD = 4;
    __shared__ float sW2[HIDDEN][C + PAD];
    __shared__ float sb2[C];

    const int tid = threadIdx.x;
    for (int t = tid; t < HIDDEN * C; t += 256) sW2[t / C][t % C] = W2[t];
    for (int t = tid; t < C; t += 256)          sb2[t] = b2[t];
    __syncthreads();

    const int local = tid >> 4;
    const int k     = tid & 15;
    const int n     = blockIdx.x * 16 + local;       // 3125*16 = 50000 exact

    const float* xp = (DIN == HIDDEN) ? (const float*)g_x1 : xin;
    float xs[DIN];
    {
        const float4* xr = reinterpret_cast<const float4*>(xp + (size_t)n * DIN);
#pragma unroll
        for (int q = 0; q < DIN / 4; q++) {
            float4 v = xr[q];
            xs[q * 4 + 0] = v.x; xs[q * 4 + 1] = v.y;
            xs[q * 4 + 2] = v.z; xs[q * 4 + 3] = v.w;
        }
    }

    float acc[HIDDEN];
#pragma unroll
    for (int o = 0; o < HIDDEN; o++) acc[o] = 0.0f;
#pragma unroll
    for (int i = 0; i < DIN; i++) {
        const float xi = xs[i];
#pragma unroll
        for (int o = 0; o < HIDDEN; o++) acc[o] += xi * sW2[k][i * HIDDEN + o];
    }
    float4* yw = reinterpret_cast<float4*>(&g_Y[(size_t)n * 256 + k * HIDDEN]);
#pragma unroll
    for (int q = 0; q < 4; q++)
        yw[q] = make_float4(acc[q * 4 + 0], acc[q * 4 + 1], acc[q * 4 + 2], acc[q * 4 + 3]);

    if (k == 0) {
        float bacc[HIDDEN];
#pragma unroll
        for (int o = 0; o < HIDDEN; o++) bacc[o] = 0.0f;
#pragma unroll
        for (int i = 0; i < DIN; i++) {
            const float xi = xs[i];
#pragma unroll
            for (int o = 0; o < HIDDEN; o++) bacc[o] += xi * sb2[i * HIDDEN + o];
        }
        float4* bw = reinterpret_cast<float4*>(&g_B[(size_t)n * HIDDEN]);
#pragma unroll
        for (int q = 0; q < 4; q++)
            bw[q] = make_float4(bacc[q * 4 + 0], bacc[q * 4 + 1], bacc[q * 4 + 2], bacc[q * 4 + 3]);
    }
}

// ---------------- CSR edge kernel ----------------
// One 16-lane group per src node. Lane o holds Y[:,o] column in registers
// (loaded ONCE per node). For each out-edge: compute h_o, all-gather h via
// width-16 shuffles, msg_o = B + sum_k h_k*Y[k,o], scalar red to agg[dst,o].
__global__ void __launch_bounds__(256)
edge_csr_kernel(const int* __restrict__ ei, const float* __restrict__ ea,
                const float* __restrict__ W1, const float* __restrict__ b1)
{
    __shared__ float sW1[EDGE_DIM * HIDDEN];
    __shared__ float sb1[HIDDEN];
    const int tid = threadIdx.x;
    if (tid < EDGE_DIM * HIDDEN) sW1[tid] = W1[tid];
    if (tid < HIDDEN)            sb1[tid] = b1[tid];
    __syncthreads();

    const int grp    = tid >> 4;                     // 0..15 within block
    const int lane   = tid & 15;                     // o index
    const int halfhi = (tid >> 4) & 1;               // which half of the warp
    const unsigned mask = 0xFFFFu << (16 * halfhi);
    const int n = blockIdx.x * 16 + grp;             // 3125*16 = 50000 exact

    // Y column for this lane (o = lane), k = 0..15
    float yreg[HIDDEN];
    const float* yb = &g_Y[(size_t)n * 256 + lane];
#pragma unroll
    for (int k = 0; k < HIDDEN; k++) yreg[k] = yb[k * HIDDEN];
    const float breg = g_B[(size_t)n * HIDDEN + lane];

    const float w0 = sW1[lane];
    const float w1 = sW1[HIDDEN + lane];
    const float w2 = sW1[2 * HIDDEN + lane];
    const float w3 = sW1[3 * HIDDEN + lane];
    const float bc = sb1[lane];

    const int beg = g_rowptr[n];
    const int end = g_rowptr[n + 1];

    for (int p = beg; p < end; p++) {
        const int e   = g_eidx[p];
        const int dst = ei[N_EDGES + e];
        const float4 a4 = reinterpret_cast<const float4*>(ea)[e];

        float v = bc + a4.x * w0 + a4.y * w1 + a4.z * w2 + a4.w * w3;
        const float h = v * sigmoidf_(v);

        float m = breg;
#pragma unroll
        for (int k = 0; k < HIDDEN; k++) {
            const float hk = __shfl_sync(mask, h, k, 16);
            m += hk * yreg[k];
        }

        asm volatile("red.global.add.f32 [%0], %1;"
                     :: "l"(&g_agg[(size_t)dst * HIDDEN + lane]), "f"(m)
                     : "memory");
    }
}

// ---------------- layer-0 node update ----------------
__global__ void __launch_bounds__(128)
node0_kernel(const float* __restrict__ x, const float* __restrict__ root,
             const float* __restrict__ bias)
{
    __shared__ float sroot[IN_DIM * HIDDEN];
    __shared__ float sbias[HIDDEN];
    const int tid = threadIdx.x;
    if (tid < IN_DIM * HIDDEN) sroot[tid] = root[tid];
    if (tid < HIDDEN)          sbias[tid] = bias[tid];
    __syncthreads();

    const int n = blockIdx.x * blockDim.x + tid;
    if (n >= N_NODES) return;

    float xs[IN_DIM];
    const float4* xr = reinterpret_cast<const float4*>(x + (size_t)n * IN_DIM);
    { float4 v = xr[0]; xs[0]=v.x; xs[1]=v.y; xs[2]=v.z; xs[3]=v.w; }
    { float4 v = xr[1]; xs[4]=v.x; xs[5]=v.y; xs[6]=v.z; xs[7]=v.w; }

    const float inv = 1.0f / fmaxf((float)g_cnti[n], 1.0f);
    float4* ar  = reinterpret_cast<float4*>(&g_agg[(size_t)n * HIDDEN]);
    float4* x1r = reinterpret_cast<float4*>(&g_x1[(size_t)n * HIDDEN]);

    float acc[HIDDEN];
#pragma unroll
    for (int q = 0; q < 4; q++) {
        float4 a = ar[q];
        acc[q * 4 + 0] = sbias[q * 4 + 0] + a.x * inv;
        acc[q * 4 + 1] = sbias[q * 4 + 1] + a.y * inv;
        acc[q * 4 + 2] = sbias[q * 4 + 2] + a.z * inv;
        acc[q * 4 + 3] = sbias[q * 4 + 3] + a.w * inv;
    }
#pragma unroll
    for (int i = 0; i < IN_DIM; i++) {
        const float xi = xs[i];
#pragma unroll
        for (int o = 0; o < HIDDEN; o++) acc[o] += xi * sroot[i * HIDDEN + o];
    }
#pragma unroll
    for (int q = 0; q < 4; q++) {
        float4 v;
        v.x = fmaxf(acc[q * 4 + 0], 0.0f);
        v.y = fmaxf(acc[q * 4 + 1], 0.0f);
        v.z = fmaxf(acc[q * 4 + 2], 0.0f);
        v.w = fmaxf(acc[q * 4 + 3], 0.0f);
        x1r[q] = v;
        ar[q] = make_float4(0.0f, 0.0f, 0.0f, 0.0f);   // rezero for layer 1
    }
}

// ---------------- layer-1 node update + MLP head ----------------
__global__ void __launch_bounds__(128)
node1_kernel(const float* __restrict__ root, const float* __restrict__ bias,
             const float* __restrict__ mW1, const float* __restrict__ mb1,
             const float* __restrict__ mW2, const float* __restrict__ mb2,
             float* __restrict__ out)
{
    __shared__ float sroot[HIDDEN * HIDDEN];
    __shared__ float smW1 [HIDDEN * HIDDEN];
    __shared__ float smW2 [HIDDEN];
    __shared__ float sbias[HIDDEN];
    __shared__ float smb1 [HIDDEN];
    __shared__ float smb2s;

    const int tid = threadIdx.x;
    for (int t = tid; t < HIDDEN * HIDDEN; t += blockDim.x) {
        sroot[t] = root[t];
        smW1[t]  = mW1[t];
    }
    if (tid < HIDDEN) { smW2[tid] = mW2[tid]; sbias[tid] = bias[tid]; smb1[tid] = mb1[tid]; }
    if (tid == 0) smb2s = mb2[0];
    __syncthreads();

    const int n = blockIdx.x * blockDim.x + tid;
    if (n >= N_NODES) return;

    float x1v[HIDDEN];
    const float4* xr = reinterpret_cast<const float4*>(&g_x1[(size_t)n * HIDDEN]);
#pragma unroll
    for (int q = 0; q < 4; q++) {
        float4 v = xr[q];
        x1v[q * 4 + 0] = v.x; x1v[q * 4 + 1] = v.y;
        x1v[q * 4 + 2] = v.z; x1v[q * 4 + 3] = v.w;
    }
    const float inv = 1.0f / fmaxf((float)g_cnti[n], 1.0f);
    const float4* ar = reinterpret_cast<const float4*>(&g_agg[(size_t)n * HIDDEN]);

    float x2[HIDDEN];
#pragma unroll
    for (int q = 0; q < 4; q++) {
        float4 a = ar[q];
        x2[q * 4 + 0] = sbias[q * 4 + 0] + a.x * inv;
        x2[q * 4 + 1] = sbias[q * 4 + 1] + a.y * inv;
        x2[q * 4 + 2] = sbias[q * 4 + 2] + a.z * inv;
        x2[q * 4 + 3] = sbias[q * 4 + 3] + a.w * inv;
    }
#pragma unroll
    for (int i = 0; i < HIDDEN; i++) {
        const float xi = x1v[i];
#pragma unroll
        for (int o = 0; o < HIDDEN; o++) x2[o] += xi * sroot[i * HIDDEN + o];
    }
#pragma unroll
    for (int o = 0; o < HIDDEN; o++) x2[o] = fmaxf(x2[o], 0.0f);

    float hm[HIDDEN];
#pragma unroll
    for (int o = 0; o < HIDDEN; o++) hm[o] = smb1[o];
#pragma unroll
    for (int i = 0; i < HIDDEN; i++) {
        const float xi = x2[i];
#pragma unroll
        for (int o = 0; o < HIDDEN; o++) hm[o] += xi * smW1[i * HIDDEN + o];
    }
    float z = smb2s;
#pragma unroll
    for (int i = 0; i < HIDDEN; i++) {
        float t = hm[i];
        z += (t * sigmoidf_(t)) * smW2[i];
    }
    out[n] = sigmoidf_(z);
}

// ---------------- launch ----------------
extern "C" void kernel_launch(void* const* d_in, const int* in_sizes, int n_in,
                              void* d_out, int out_size)
{
    const float* x      = (const float*)d_in[0];
    const int*   ei     = (const int*)  d_in[1];
    const float* ea     = (const float*)d_in[2];
    const float* eW1_0  = (const float*)d_in[3];
    const float* eb1_0  = (const float*)d_in[4];
    const float* eW2_0  = (const float*)d_in[5];
    const float* eb2_0  = (const float*)d_in[6];
    const float* root_0 = (const float*)d_in[7];
    const float* bias_0 = (const float*)d_in[8];
    const float* eW1_1  = (const float*)d_in[9];
    const float* eb1_1  = (const float*)d_in[10];
    const float* eW2_1  = (const float*)d_in[11];
    const float* eb2_1  = (const float*)d_in[12];
    const float* root_1 = (const float*)d_in[13];
    const float* bias_1 = (const float*)d_in[14];
    const float* mW1    = (const float*)d_in[15];
    const float* mb1    = (const float*)d_in[16];
    const float* mW2    = (const float*)d_in[17];
    const float* mb2    = (const float*)d_in[18];
    float* out = (float*)d_out;

    const int ZB = 256;
    const int ZG = (N_NODES * HIDDEN + ZB - 1) / ZB;   // 3125
    const int HG = (N_EDGES + 255) / 256;              // 3125
    const int YG = N_NODES / 16;                       // 3125 exact
    const int CG = N_NODES / 16;                       // 3125 exact (16 groups/block)
    const int NB = 128;
    const int NG = (N_NODES + NB - 1) / NB;            // 391

    zero_kernel   <<<ZG, ZB>>>();
    hist_kernel   <<<HG, 256>>>(ei);
    scan_kernel   <<<1, 1024>>>();
    scatter_kernel<<<HG, 256>>>(ei);

    y_kernel<IN_DIM><<<YG, 256>>>(x, eW2_0, eb2_0);
    edge_csr_kernel <<<CG, 256>>>(ei, ea, eW1_0, eb1_0);
    node0_kernel    <<<NG, NB>>>(x, root_0, bias_0);

    y_kernel<HIDDEN><<<YG, 256>>>(nullptr, eW2_1, eb2_1);
    edge_csr_kernel <<<CG, 256>>>(ei, ea, eW1_1, eb1_1);
    node1_kernel    <<<NG, NB>>>(root_1, bias_1, mW1, mb1, mW2, mb2, out);
}

// round 17
// speedup vs baseline: 1.1820x; 1.1820x over previous
#include <cuda_runtime.h>
#include <cstdint>

#define N_NODES 50000
#define N_EDGES 800000
#define IN_DIM  8
#define EDGE_DIM 4
#define HIDDEN  16

// ---------------- scratch (device globals; no allocation allowed) ----------------
__device__ float g_x1 [N_NODES * HIDDEN];           // layer-0 output
__device__ float g_agg[N_NODES * HIDDEN];           // scatter accumulator
__device__ float g_Y  [N_NODES * HIDDEN * HIDDEN];  // per-node contracted weights [n][k][o]
__device__ float g_B  [N_NODES * HIDDEN];           // per-node contracted bias    [n][o]
__device__ int   g_deg   [N_NODES];                 // out-degree (src histogram)
__device__ int   g_cnti  [N_NODES];                 // in-degree  (dst histogram)
__device__ int   g_pos   [N_NODES];                 // scatter cursors
__device__ int   g_eidx  [N_EDGES];                 // edge ids grouped by src

__device__ __forceinline__ float sigmoidf_(float x) {
    return 1.0f / (1.0f + __expf(-x));
}

// ---------------- zero ----------------
__global__ void zero_kernel() {
    int i = blockIdx.x * blockDim.x + threadIdx.x;
    if (i < N_NODES * HIDDEN) g_agg[i] = 0.0f;
    if (i < N_NODES) { g_deg[i] = 0; g_cnti[i] = 0; }
}

// ---------------- histogram (src out-degree, dst in-degree) ----------------
__global__ void hist_kernel(const int* __restrict__ ei) {
    int e = blockIdx.x * blockDim.x + threadIdx.x;
    if (e >= N_EDGES) return;
    atomicAdd(&g_deg [ei[e]], 1);
    atomicAdd(&g_cnti[ei[N_EDGES + e]], 1);
}

// ---------------- exclusive scan of degrees -> pos cursors ----------------
__global__ void __launch_bounds__(1024)
scan_kernel() {
    __shared__ int part[1024];
    const int t = threadIdx.x;
    const int CH = (N_NODES + 1023) / 1024;          // 49
    const int beg = t * CH;
    const int end = min(beg + CH, N_NODES);
    int s = 0;
    for (int i = beg; i < end; i++) s += g_deg[i];
    part[t] = s;
    __syncthreads();
    for (int off = 1; off < 1024; off <<= 1) {
        int v = (t >= off) ? part[t - off] : 0;
        __syncthreads();
        part[t] += v;
        __syncthreads();
    }
    int run = (t == 0) ? 0 : part[t - 1];
    for (int i = beg; i < end; i++) {
        g_pos[i] = run;
        run += g_deg[i];
    }
}

// ---------------- scatter edge ids into src-sorted order ----------------
__global__ void scatter_kernel(const int* __restrict__ ei) {
    int e = blockIdx.x * blockDim.x + threadIdx.x;
    if (e >= N_EDGES) return;
    int p = atomicAdd(&g_pos[ei[e]], 1);
    g_eidx[p] = e;
}

// ---------------- Y precompute ----------------
// Y[n,k,o] = sum_i x[n,i] * W2[k, i*16+o];  B[n,o] = sum_i x[n,i] * b2[i*16+o]
template<int DIN>
__global__ void __launch_bounds__(256)
y_kernel(const float* __restrict__ xin,
         const float* __restrict__ W2, const float* __restrict__ b2)
{
    constexpr int C = DIN * HIDDEN;
    constexpr int PAD = 4;
    __shared__ float sW2[HIDDEN][C + PAD];
    __shared__ float sb2[C];

    const int tid = threadIdx.x;
    for (int t = tid; t < HIDDEN * C; t += 256) sW2[t / C][t % C] = W2[t];
    for (int t = tid; t < C; t += 256)          sb2[t] = b2[t];
    __syncthreads();

    const int local = tid >> 4;
    const int k     = tid & 15;
    const int n     = blockIdx.x * 16 + local;       // 3125*16 = 50000 exact

    const float* xp = (DIN == HIDDEN) ? (const float*)g_x1 : xin;
    float xs[DIN];
    {
        const float4* xr = reinterpret_cast<const float4*>(xp + (size_t)n * DIN);
#pragma unroll
        for (int q = 0; q < DIN / 4; q++) {
            float4 v = xr[q];
            xs[q * 4 + 0] = v.x; xs[q * 4 + 1] = v.y;
            xs[q * 4 + 2] = v.z; xs[q * 4 + 3] = v.w;
        }
    }

    float acc[HIDDEN];
#pragma unroll
    for (int o = 0; o < HIDDEN; o++) acc[o] = 0.0f;
#pragma unroll
    for (int i = 0; i < DIN; i++) {
        const float xi = xs[i];
#pragma unroll
        for (int o = 0; o < HIDDEN; o++) acc[o] += xi * sW2[k][i * HIDDEN + o];
    }
    float4* yw = reinterpret_cast<float4*>(&g_Y[(size_t)n * 256 + k * HIDDEN]);
#pragma unroll
    for (int q = 0; q < 4; q++)
        yw[q] = make_float4(acc[q * 4 + 0], acc[q * 4 + 1], acc[q * 4 + 2], acc[q * 4 + 3]);

    if (k == 0) {
        float bacc[HIDDEN];
#pragma unroll
        for (int o = 0; o < HIDDEN; o++) bacc[o] = 0.0f;
#pragma unroll
        for (int i = 0; i < DIN; i++) {
            const float xi = xs[i];
#pragma unroll
            for (int o = 0; o < HIDDEN; o++) bacc[o] += xi * sb2[i * HIDDEN + o];
        }
        float4* bw = reinterpret_cast<float4*>(&g_B[(size_t)n * HIDDEN]);
#pragma unroll
        for (int q = 0; q < 4; q++)
            bw[q] = make_float4(bacc[q * 4 + 0], bacc[q * 4 + 1], bacc[q * 4 + 2], bacc[q * 4 + 3]);
    }
}

// ---------------- edge kernel: parallel 4-lane/edge, src-sorted iteration ----
// Thread quad processes sorted-edge position p = blockIdx*64 + (tid>>2);
// consecutive p share src -> Y row L1-resident after first fetch.
// lane r owns o-quad [4r, 4r+4): msg = B[src] + sum_k h_k * Y[src,k,:].
__global__ void __launch_bounds__(256)
edge_y_kernel(const int* __restrict__ ei, const float* __restrict__ ea,
              const float* __restrict__ W1, const float* __restrict__ b1)
{
    __shared__ float sW1[EDGE_DIM * HIDDEN];
    __shared__ float sb1[HIDDEN];
    __shared__ float sh[64][HIDDEN + 1];

    const int tid = threadIdx.x;
    if (tid < EDGE_DIM * HIDDEN) sW1[tid] = W1[tid];
    if (tid < HIDDEN)            sb1[tid] = b1[tid];
    __syncthreads();

    const int el = tid >> 2;                         // sorted-edge slot in block
    const int r  = tid & 3;                          // o-quad index
    const int p  = blockIdx.x * 64 + el;             // 12500 * 64 = 800000 exact
    const int e  = g_eidx[p];

    // ---- phase 1: h (each lane computes 4 of the 16 j's) ----
    const float4 a4 = reinterpret_cast<const float4*>(ea)[e];
#pragma unroll
    for (int jj = 0; jj < 4; jj++) {
        const int j = r * 4 + jj;
        float v = sb1[j] + a4.x * sW1[j] + a4.y * sW1[HIDDEN + j]
                         + a4.z * sW1[2 * HIDDEN + j] + a4.w * sW1[3 * HIDDEN + j];
        sh[el][j] = v * sigmoidf_(v);
    }
    __syncwarp();

    // ---- phase 2: msg quad from Y (L1-resident via src-sorted reuse) ----
    const int src = ei[e];
    const int dst = ei[N_EDGES + e];

    const float* yrow = &g_Y[(size_t)src * 256 + r * 4];
    float4 m = *reinterpret_cast<const float4*>(&g_B[(size_t)src * HIDDEN + r * 4]);

#pragma unroll
    for (int k = 0; k < HIDDEN; k++) {
        const float hk = sh[el][k];
        const float4 w = *reinterpret_cast<const float4*>(yrow + k * HIDDEN);
        m.x += hk * w.x;
        m.y += hk * w.y;
        m.z += hk * w.z;
        m.w += hk * w.w;
    }

    float* base = &g_agg[(size_t)dst * HIDDEN + r * 4];
    asm volatile("red.global.add.v4.f32 [%0], {%1,%2,%3,%4};"
                 :: "l"(base), "f"(m.x), "f"(m.y), "f"(m.z), "f"(m.w)
                 : "memory");
}

// ---------------- layer-0 node update ----------------
__global__ void __launch_bounds__(128)
node0_kernel(const float* __restrict__ x, const float* __restrict__ root,
             const float* __restrict__ bias)
{
    __shared__ float sroot[IN_DIM * HIDDEN];
    __shared__ float sbias[HIDDEN];
    const int tid = threadIdx.x;
    if (tid < IN_DIM * HIDDEN) sroot[tid] = root[tid];
    if (tid < HIDDEN)          sbias[tid] = bias[tid];
    __syncthreads();

    const int n = blockIdx.x * blockDim.x + tid;
    if (n >= N_NODES) return;

    float xs[IN_DIM];
    const float4* xr = reinterpret_cast<const float4*>(x + (size_t)n * IN_DIM);
    { float4 v = xr[0]; xs[0]=v.x; xs[1]=v.y; xs[2]=v.z; xs[3]=v.w; }
    { float4 v = xr[1]; xs[4]=v.x; xs[5]=v.y; xs[6]=v.z; xs[7]=v.w; }

    const float inv = 1.0f / fmaxf((float)g_cnti[n], 1.0f);
    float4* ar  = reinterpret_cast<float4*>(&g_agg[(size_t)n * HIDDEN]);
    float4* x1r = reinterpret_cast<float4*>(&g_x1[(size_t)n * HIDDEN]);

    float acc[HIDDEN];
#pragma unroll
    for (int q = 0; q < 4; q++) {
        float4 a = ar[q];
        acc[q * 4 + 0] = sbias[q * 4 + 0] + a.x * inv;
        acc[q * 4 + 1] = sbias[q * 4 + 1] + a.y * inv;
        acc[q * 4 + 2] = sbias[q * 4 + 2] + a.z * inv;
        acc[q * 4 + 3] = sbias[q * 4 + 3] + a.w * inv;
    }
#pragma unroll
    for (int i = 0; i < IN_DIM; i++) {
        const float xi = xs[i];
#pragma unroll
        for (int o = 0; o < HIDDEN; o++) acc[o] += xi * sroot[i * HIDDEN + o];
    }
#pragma unroll
    for (int q = 0; q < 4; q++) {
        float4 v;
        v.x = fmaxf(acc[q * 4 + 0], 0.0f);
        v.y = fmaxf(acc[q * 4 + 1], 0.0f);
        v.z = fmaxf(acc[q * 4 + 2], 0.0f);
        v.w = fmaxf(acc[q * 4 + 3], 0.0f);
        x1r[q] = v;
        ar[q] = make_float4(0.0f, 0.0f, 0.0f, 0.0f);   // rezero for layer 1
    }
}

// ---------------- layer-1 node update + MLP head ----------------
__global__ void __launch_bounds__(128)
node1_kernel(const float* __restrict__ root, const float* __restrict__ bias,
             const float* __restrict__ mW1, const float* __restrict__ mb1,
             const float* __restrict__ mW2, const float* __restrict__ mb2,
             float* __restrict__ out)
{
    __shared__ float sroot[HIDDEN * HIDDEN];
    __shared__ float smW1 [HIDDEN * HIDDEN];
    __shared__ float smW2 [HIDDEN];
    __shared__ float sbias[HIDDEN];
    __shared__ float smb1 [HIDDEN];
    __shared__ float smb2s;

    const int tid = threadIdx.x;
    for (int t = tid; t < HIDDEN * HIDDEN; t += blockDim.x) {
        sroot[t] = root[t];
        smW1[t]  = mW1[t];
    }
    if (tid < HIDDEN) { smW2[tid] = mW2[tid]; sbias[tid] = bias[tid]; smb1[tid] = mb1[tid]; }
    if (tid == 0) smb2s = mb2[0];
    __syncthreads();

    const int n = blockIdx.x * blockDim.x + tid;
    if (n >= N_NODES) return;

    float x1v[HIDDEN];
    const float4* xr = reinterpret_cast<const float4*>(&g_x1[(size_t)n * HIDDEN]);
#pragma unroll
    for (int q = 0; q < 4; q++) {
        float4 v = xr[q];
        x1v[q * 4 + 0] = v.x; x1v[q * 4 + 1] = v.y;
        x1v[q * 4 + 2] = v.z; x1v[q * 4 + 3] = v.w;
    }
    const float inv = 1.0f / fmaxf((float)g_cnti[n], 1.0f);
    const float4* ar = reinterpret_cast<const float4*>(&g_agg[(size_t)n * HIDDEN]);

    float x2[HIDDEN];
#pragma unroll
    for (int q = 0; q < 4; q++) {
        float4 a = ar[q];
        x2[q * 4 + 0] = sbias[q * 4 + 0] + a.x * inv;
        x2[q * 4 + 1] = sbias[q * 4 + 1] + a.y * inv;
        x2[q * 4 + 2] = sbias[q * 4 + 2] + a.z * inv;
        x2[q * 4 + 3] = sbias[q * 4 + 3] + a.w * inv;
    }
#pragma unroll
    for (int i = 0; i < HIDDEN; i++) {
        const float xi = x1v[i];
#pragma unroll
        for (int o = 0; o < HIDDEN; o++) x2[o] += xi * sroot[i * HIDDEN + o];
    }
#pragma unroll
    for (int o = 0; o < HIDDEN; o++) x2[o] = fmaxf(x2[o], 0.0f);

    float hm[HIDDEN];
#pragma unroll
    for (int o = 0; o < HIDDEN; o++) hm[o] = smb1[o];
#pragma unroll
    for (int i = 0; i < HIDDEN; i++) {
        const float xi = x2[i];
#pragma unroll
        for (int o = 0; o < HIDDEN; o++) hm[o] += xi * smW1[i * HIDDEN + o];
    }
    float z = smb2s;
#pragma unroll
    for (int i = 0; i < HIDDEN; i++) {
        float t = hm[i];
        z += (t * sigmoidf_(t)) * smW2[i];
    }
    out[n] = sigmoidf_(z);
}

// ---------------- launch ----------------
extern "C" void kernel_launch(void* const* d_in, const int* in_sizes, int n_in,
                              void* d_out, int out_size)
{
    const float* x      = (const float*)d_in[0];
    const int*   ei     = (const int*)  d_in[1];
    const float* ea     = (const float*)d_in[2];
    const float* eW1_0  = (const float*)d_in[3];
    const float* eb1_0  = (const float*)d_in[4];
    const float* eW2_0  = (const float*)d_in[5];
    const float* eb2_0  = (const float*)d_in[6];
    const float* root_0 = (const float*)d_in[7];
    const float* bias_0 = (const float*)d_in[8];
    const float* eW1_1  = (const float*)d_in[9];
    const float* eb1_1  = (const float*)d_in[10];
    const float* eW2_1  = (const float*)d_in[11];
    const float* eb2_1  = (const float*)d_in[12];
    const float* root_1 = (const float*)d_in[13];
    const float* bias_1 = (const float*)d_in[14];
    const float* mW1    = (const float*)d_in[15];
    const float* mb1    = (const float*)d_in[16];
    const float* mW2    = (const float*)d_in[17];
    const float* mb2    = (const float*)d_in[18];
    float* out = (float*)d_out;

    const int ZB = 256;
    const int ZG = (N_NODES * HIDDEN + ZB - 1) / ZB;   // 3125
    const int HG = (N_EDGES + 255) / 256;              // 3125
    const int YG = N_NODES / 16;                       // 3125 exact
    const int EG = N_EDGES * 4 / 256;                  // 12500 exact
    const int NB = 128;
    const int NG = (N_NODES + NB - 1) / NB;            // 391

    zero_kernel   <<<ZG, ZB>>>();
    hist_kernel   <<<HG, 256>>>(ei);
    scan_kernel   <<<1, 1024>>>();
    scatter_kernel<<<HG, 256>>>(ei);

    y_kernel<IN_DIM><<<YG, 256>>>(x, eW2_0, eb2_0);
    edge_y_kernel   <<<EG, 256>>>(ei, ea, eW1_0, eb1_0);
    node0_kernel    <<<NG, NB>>>(x, root_0, bias_0);

    y_kernel<HIDDEN><<<YG, 256>>>(nullptr, eW2_1, eb2_1);
    edge_y_kernel   <<<EG, 256>>>(ei, ea, eW1_1, eb1_1);
    node1_kernel    <<<NG, NB>>>(root_1, bias_1, mW1, mb1, mW2, mb2, out);
}